// round 6
// baseline (speedup 1.0000x reference)
#include <cuda_runtime.h>
#include <cstdint>

// Problem constants
#define NB 4
#define NS 1024
#define ND 1024
#define NH 16
#define DH 64
#define NM (NB * NS)   // 4096 rows

// Scratch (allocation-free rule: __device__ globals)
__device__ float g_xn[NM * ND];          // layernormed input [4096,1024]
__device__ float g_q[NM * ND];           // q as [B*H][S][64]
__device__ float g_k[NM * ND];
__device__ float g_v[NM * ND];

// ---------------------------------------------------------------------------
// helpers
// ---------------------------------------------------------------------------
__device__ __forceinline__ uint32_t f2tf32(float f) {
    uint32_t u;
    asm("cvt.rna.tf32.f32 %0, %1;" : "=r"(u) : "f"(f));
    return u;
}
__device__ __forceinline__ float tf32rf(float f) {
    return __uint_as_float(f2tf32(f));
}

__device__ __forceinline__ void mma_tf32(float c[4],
                                         uint32_t a0, uint32_t a1, uint32_t a2, uint32_t a3,
                                         uint32_t b0, uint32_t b1) {
    asm volatile(
        "mma.sync.aligned.m16n8k8.row.col.f32.tf32.tf32.f32 "
        "{%0,%1,%2,%3},{%4,%5,%6,%7},{%8,%9},{%0,%1,%2,%3};\n"
        : "+f"(c[0]), "+f"(c[1]), "+f"(c[2]), "+f"(c[3])
        : "r"(a0), "r"(a1), "r"(a2), "r"(a3), "r"(b0), "r"(b1));
}

__device__ __forceinline__ void cp16(float* smem, const float* gmem) {
    uint32_t sa = (uint32_t)__cvta_generic_to_shared(smem);
    asm volatile("cp.async.ca.shared.global [%0], [%1], 16;\n" :: "r"(sa), "l"(gmem));
}

// ---------------------------------------------------------------------------
// Kernel 1: LayerNorm. One block per row (4096 rows), 256 threads, float4.
// ---------------------------------------------------------------------------
__global__ void __launch_bounds__(256)
ln_kernel(const float* __restrict__ x,
          const float* __restrict__ gamma,
          const float* __restrict__ beta) {
    int row = blockIdx.x;
    int tid = threadIdx.x;
    const float4* xr = reinterpret_cast<const float4*>(x + (size_t)row * ND);
    float4 v = xr[tid];

    float s1 = v.x + v.y + v.z + v.w;
    float s2 = v.x * v.x + v.y * v.y + v.z * v.z + v.w * v.w;

    __shared__ float red1[8];
    __shared__ float red2[8];
    #pragma unroll
    for (int o = 16; o; o >>= 1) {
        s1 += __shfl_xor_sync(0xffffffffu, s1, o);
        s2 += __shfl_xor_sync(0xffffffffu, s2, o);
    }
    if ((tid & 31) == 0) { red1[tid >> 5] = s1; red2[tid >> 5] = s2; }
    __syncthreads();
    if (tid == 0) {
        float t1 = 0.f, t2 = 0.f;
        #pragma unroll
        for (int i = 0; i < 8; i++) { t1 += red1[i]; t2 += red2[i]; }
        red1[0] = t1; red2[0] = t2;
    }
    __syncthreads();
    float mu = red1[0] * (1.0f / ND);
    float var = red2[0] * (1.0f / ND) - mu * mu;
    float rstd = rsqrtf(var + 1e-5f);

    const float4 g4 = reinterpret_cast<const float4*>(gamma)[tid];
    const float4 b4 = reinterpret_cast<const float4*>(beta)[tid];
    float4 o;
    o.x = (v.x - mu) * rstd * g4.x + b4.x;
    o.y = (v.y - mu) * rstd * g4.y + b4.y;
    o.z = (v.z - mu) * rstd * g4.z + b4.z;
    o.w = (v.w - mu) * rstd * g4.w + b4.w;
    reinterpret_cast<float4*>(g_xn + (size_t)row * ND)[tid] = o;
}

// ---------------------------------------------------------------------------
// Kernel 2: QKV projection GEMM, tf32 + cp.async 2-stage pipeline.
// C[4096,1024] = xn @ W + b, z selects q/k/v.
// 128x128 block tile, BK=32, 256 threads, 8 warps each computing 64x32 via
// m16n8k8 mmas. Raw f32 staged through smem; cvt.rna to tf32 at fragment load.
// ---------------------------------------------------------------------------
#define A_STRIDE 36
#define B_STRIDE 136
#define A_STAGE (128 * A_STRIDE)
#define B_STAGE (32 * B_STRIDE)
#define QKV_SMEM ((2 * A_STAGE + 2 * B_STAGE) * 4)   // 71680 bytes

__global__ void __launch_bounds__(256)
qkv_gemm(const float* __restrict__ Wq, const float* __restrict__ bq,
         const float* __restrict__ Wk, const float* __restrict__ bk,
         const float* __restrict__ Wv, const float* __restrict__ bv) {
    extern __shared__ float smq[];
    float* Asm = smq;                    // [2][128][36]
    float* Bsm = smq + 2 * A_STAGE;      // [2][32][136]

    int z = blockIdx.z;
    const float* W    = (z == 0) ? Wq : (z == 1) ? Wk : Wv;
    const float* bias = (z == 0) ? bq : (z == 1) ? bk : bv;
    float* outp       = (z == 0) ? g_q : (z == 1) ? g_k : g_v;

    int tid  = threadIdx.x;
    int lane = tid & 31;
    int warp = tid >> 5;
    int wm = warp & 1;
    int wn = warp >> 1;
    int m_base = wm * 64;
    int n_base = wn * 32;
    int qrow = lane >> 2;
    int qcol = lane & 3;

    int m0 = blockIdx.y << 7;
    int n0 = blockIdx.x << 7;

    float acc[4][4][4];
    #pragma unroll
    for (int mt = 0; mt < 4; mt++)
        #pragma unroll
        for (int nt = 0; nt < 4; nt++)
            #pragma unroll
            for (int r = 0; r < 4; r++) acc[mt][nt][r] = 0.f;

    // async-copy addressing
    int a_r = tid >> 3;          // 0..31
    int a_c = (tid & 7) << 2;    // 0..28 (16B aligned)
    int b_r = tid >> 5;          // 0..7
    int b_c = (tid & 31) << 2;   // 0..124 (16B aligned)

    const float* agp = g_xn + (size_t)(m0 + a_r) * ND + a_c;
    const float* bgp = W + (size_t)b_r * ND + n0 + b_c;

    #define QKV_ISSUE(s, k0)                                                    \
        do {                                                                    \
            float* as_ = Asm + (s) * A_STAGE;                                   \
            float* bs_ = Bsm + (s) * B_STAGE;                                   \
            _Pragma("unroll")                                                   \
            for (int i_ = 0; i_ < 4; i_++)                                      \
                cp16(as_ + (a_r + 32 * i_) * A_STRIDE + a_c,                    \
                     agp + (size_t)(32 * i_) * ND + (k0));                      \
            _Pragma("unroll")                                                   \
            for (int i_ = 0; i_ < 4; i_++)                                      \
                cp16(bs_ + (b_r + 8 * i_) * B_STRIDE + b_c,                     \
                     bgp + (size_t)((k0) + 8 * i_) * ND);                       \
            asm volatile("cp.async.commit_group;\n");                           \
        } while (0)

    QKV_ISSUE(0, 0);

    for (int it = 0; it < 32; it++) {
        if (it + 1 < 32) {
            QKV_ISSUE((it + 1) & 1, (it + 1) * 32);
            asm volatile("cp.async.wait_group 1;\n");
        } else {
            asm volatile("cp.async.wait_group 0;\n");
        }
        __syncthreads();

        const float* As = Asm + (it & 1) * A_STAGE;
        const float* Bs = Bsm + (it & 1) * B_STAGE;

        #pragma unroll
        for (int ks = 0; ks < 4; ks++) {
            int kk = ks * 8;
            uint32_t af[4][4];
            #pragma unroll
            for (int mt = 0; mt < 4; mt++) {
                int r = m_base + mt * 16 + qrow;
                af[mt][0] = f2tf32(As[r * A_STRIDE + kk + qcol]);
                af[mt][1] = f2tf32(As[(r + 8) * A_STRIDE + kk + qcol]);
                af[mt][2] = f2tf32(As[r * A_STRIDE + kk + qcol + 4]);
                af[mt][3] = f2tf32(As[(r + 8) * A_STRIDE + kk + qcol + 4]);
            }
            uint32_t bf[4][2];
            #pragma unroll
            for (int nt = 0; nt < 4; nt++) {
                int c = n_base + nt * 8 + qrow;
                bf[nt][0] = f2tf32(Bs[(kk + qcol) * B_STRIDE + c]);
                bf[nt][1] = f2tf32(Bs[(kk + qcol + 4) * B_STRIDE + c]);
            }
            #pragma unroll
            for (int mt = 0; mt < 4; mt++)
                #pragma unroll
                for (int nt = 0; nt < 4; nt++)
                    mma_tf32(acc[mt][nt],
                             af[mt][0], af[mt][1], af[mt][2], af[mt][3],
                             bf[nt][0], bf[nt][1]);
        }
        __syncthreads();
    }
    #undef QKV_ISSUE

    #pragma unroll
    for (int mt = 0; mt < 4; mt++) {
        #pragma unroll
        for (int nt = 0; nt < 4; nt++) {
            int col = n0 + n_base + nt * 8 + 2 * qcol;
            int h = col >> 6, d = col & 63;
            float bx = bias[col], by = bias[col + 1];
            #pragma unroll
            for (int half = 0; half < 2; half++) {
                int row = m0 + m_base + mt * 16 + qrow + half * 8;
                int b_ = row >> 10, s = row & 1023;
                float2 v;
                v.x = acc[mt][nt][half * 2 + 0] + bx;
                v.y = acc[mt][nt][half * 2 + 1] + by;
                *(float2*)(outp + (size_t)(((b_ * NH + h) << 10) + s) * DH + d) = v;
            }
        }
    }
}

// ---------------------------------------------------------------------------
// Kernel 3: attention, tf32 tensor-core version (unchanged from R4).
// ---------------------------------------------------------------------------
#define ATTN_SMEM ((64 * 68 * 2 + 64 * 72 * 2 + 64) * 4)

__global__ void __launch_bounds__(256)
attn_kernel(const float* __restrict__ x,
            const int* __restrict__ kvlen,
            float* __restrict__ out_seq,
            float* __restrict__ out_attn) {
    extern __shared__ float sm[];
    float* Qs    = sm;                  // [64][68] tf32, A-operand
    float* Ps    = Qs + 64 * 68;        // [64][68] tf32 exp vals, A-operand
    float* KsT   = Ps + 64 * 68;        // [64][72] tf32, [d][j], B-operand
    float* Vs    = KsT + 64 * 72;       // [64][72] tf32, [j][dv], B-operand
    float* rsums = Vs + 64 * 72;        // [64]

    int tid  = threadIdx.x;
    int lane = tid & 31;
    int warp = tid >> 5;
    int m_base = (warp >> 1) << 4;      // 0,16,32,48
    int n_base = (warp & 1) << 5;       // 0,32
    int qrow = lane >> 2;               // 0..7
    int qcol = lane & 3;                // 0..3

    int bh = blockIdx.y;
    int b_ = bh >> 4, h = bh & 15;
    int q0 = blockIdx.x << 6;
    int kv = kvlen[b_];

    // load Q tile (tf32-rounded)
    const float4* qbase = reinterpret_cast<const float4*>(g_q + (size_t)(bh * NS + q0) * DH);
    for (int i = tid; i < 1024; i += 256) {
        float4 q4 = qbase[i];
        int r = i >> 4, c = (i & 15) << 2;
        Qs[r * 68 + c + 0] = tf32rf(q4.x);
        Qs[r * 68 + c + 1] = tf32rf(q4.y);
        Qs[r * 68 + c + 2] = tf32rf(q4.z);
        Qs[r * 68 + c + 3] = tf32rf(q4.w);
    }
    if (tid < 64) rsums[tid] = 0.f;

    float acc_o[4][4];
    #pragma unroll
    for (int nt = 0; nt < 4; nt++)
        #pragma unroll
        for (int r = 0; r < 4; r++) acc_o[nt][r] = 0.f;

    int qg0 = q0 + m_base + qrow;
    int qg1 = qg0 + 8;

    int jend = min(q0 + 64, kv);

    for (int j0 = 0; j0 < jend; j0 += 64) {
        __syncthreads();   // protects Ps/KsT/Vs reuse from previous iteration

        // K chunk -> KsT[d][j] (tf32)
        const float* kbase = g_k + (size_t)(bh * NS + j0) * DH;
        for (int idx = tid; idx < 1024; idx += 256) {
            int r = idx >> 4;
            int c4 = (idx & 15) << 2;
            float4 k4 = reinterpret_cast<const float4*>(kbase + (size_t)r * DH)[idx & 15];
            KsT[(c4 + 0) * 72 + r] = tf32rf(k4.x);
            KsT[(c4 + 1) * 72 + r] = tf32rf(k4.y);
            KsT[(c4 + 2) * 72 + r] = tf32rf(k4.z);
            KsT[(c4 + 3) * 72 + r] = tf32rf(k4.w);
        }
        // V chunk -> Vs[j][dv] (tf32)
        const float* vbase = g_v + (size_t)(bh * NS + j0) * DH;
        for (int idx = tid; idx < 1024; idx += 256) {
            int r = idx >> 4, c = idx & 15;
            float4 v4 = reinterpret_cast<const float4*>(vbase + (size_t)r * DH)[c];
            float4 t;
            t.x = tf32rf(v4.x); t.y = tf32rf(v4.y);
            t.z = tf32rf(v4.z); t.w = tf32rf(v4.w);
            *(float4*)&Vs[r * 72 + (c << 2)] = t;
        }
        __syncthreads();

        // S = Q K^T (each warp: m16 x n32)
        float acc_s[4][4];
        #pragma unroll
        for (int nt = 0; nt < 4; nt++)
            #pragma unroll
            for (int r = 0; r < 4; r++) acc_s[nt][r] = 0.f;

        #pragma unroll
        for (int ks = 0; ks < 8; ks++) {
            int kk = ks * 8;
            uint32_t a0 = __float_as_uint(Qs[(m_base + qrow) * 68 + kk + qcol]);
            uint32_t a1 = __float_as_uint(Qs[(m_base + qrow + 8) * 68 + kk + qcol]);
            uint32_t a2 = __float_as_uint(Qs[(m_base + qrow) * 68 + kk + qcol + 4]);
            uint32_t a3 = __float_as_uint(Qs[(m_base + qrow + 8) * 68 + kk + qcol + 4]);
            #pragma unroll
            for (int nt = 0; nt < 4; nt++) {
                int n = n_base + nt * 8 + qrow;
                uint32_t b0 = __float_as_uint(KsT[(kk + qcol) * 72 + n]);
                uint32_t b1 = __float_as_uint(KsT[(kk + qcol + 4) * 72 + n]);
                mma_tf32(acc_s[nt], a0, a1, a2, a3, b0, b1);
            }
        }

        // mask + exp on fragments; store tf32-rounded into Ps
        #pragma unroll
        for (int nt = 0; nt < 4; nt++) {
            int kl = n_base + nt * 8 + 2 * qcol;
            int kg = j0 + kl;
            float e0 = (kg     <= qg0 && kg     < kv) ? __expf(acc_s[nt][0] * 0.125f) : 0.f;
            float e1 = (kg + 1 <= qg0 && kg + 1 < kv) ? __expf(acc_s[nt][1] * 0.125f) : 0.f;
            float e2 = (kg     <= qg1 && kg     < kv) ? __expf(acc_s[nt][2] * 0.125f) : 0.f;
            float e3 = (kg + 1 <= qg1 && kg + 1 < kv) ? __expf(acc_s[nt][3] * 0.125f) : 0.f;
            e0 = tf32rf(e0); e1 = tf32rf(e1); e2 = tf32rf(e2); e3 = tf32rf(e3);
            *(float2*)&Ps[(m_base + qrow) * 68 + kl]     = make_float2(e0, e1);
            *(float2*)&Ps[(m_base + qrow + 8) * 68 + kl] = make_float2(e2, e3);
        }
        __syncthreads();

        // rowsum reduce + unnormalized global write (from Ps)
        {
            int row = tid >> 2, part = tid & 3;
            const float* pr = Ps + row * 68 + part * 16;
            float4 p0 = *(const float4*)(pr + 0);
            float4 p1 = *(const float4*)(pr + 4);
            float4 p2 = *(const float4*)(pr + 8);
            float4 p3 = *(const float4*)(pr + 12);
            float s = p0.x + p0.y + p0.z + p0.w + p1.x + p1.y + p1.z + p1.w
                    + p2.x + p2.y + p2.z + p2.w + p3.x + p3.y + p3.z + p3.w;
            s += __shfl_xor_sync(0xffffffffu, s, 1);
            s += __shfl_xor_sync(0xffffffffu, s, 2);
            if (part == 0) rsums[row] += s;
            float* gp = out_attn + (((size_t)(bh << 10 | (q0 + row))) << 10) + j0 + part * 16;
            *(float4*)(gp + 0)  = p0;
            *(float4*)(gp + 4)  = p1;
            *(float4*)(gp + 8)  = p2;
            *(float4*)(gp + 12) = p3;
        }

        // O += P @ V
        #pragma unroll
        for (int ks = 0; ks < 8; ks++) {
            int kk = ks * 8;
            uint32_t a0 = __float_as_uint(Ps[(m_base + qrow) * 68 + kk + qcol]);
            uint32_t a1 = __float_as_uint(Ps[(m_base + qrow + 8) * 68 + kk + qcol]);
            uint32_t a2 = __float_as_uint(Ps[(m_base + qrow) * 68 + kk + qcol + 4]);
            uint32_t a3 = __float_as_uint(Ps[(m_base + qrow + 8) * 68 + kk + qcol + 4]);
            #pragma unroll
            for (int nt = 0; nt < 4; nt++) {
                int n = n_base + nt * 8 + qrow;
                uint32_t b0 = __float_as_uint(Vs[(kk + qcol) * 72 + n]);
                uint32_t b1 = __float_as_uint(Vs[(kk + qcol + 4) * 72 + n]);
                mma_tf32(acc_o[nt], a0, a1, a2, a3, b0, b1);
            }
        }
    }
    __syncthreads();

    // normalize attn rows + zero-fill masked region (full 1024 cols per row)
    {
        int ty = tid >> 4, tx = tid & 15;
        #pragma unroll
        for (int i = 0; i < 4; i++) {
            int rloc = ty * 4 + i;
            int q = q0 + rloc;
            float inv = 1.0f / rsums[rloc];
            float* rowp = out_attn + (((size_t)(bh << 10 | q)) << 10);
            int kvq = min(q + 1, kv);   // valid k in [0, kvq)
            for (int c4 = tx * 4; c4 < 1024; c4 += 64) {
                float4 v;
                if (c4 + 4 <= kvq) {
                    v = *(float4*)(rowp + c4);
                    v.x *= inv; v.y *= inv; v.z *= inv; v.w *= inv;
                } else if (c4 >= kvq) {
                    v = make_float4(0.f, 0.f, 0.f, 0.f);
                } else {
                    v = *(float4*)(rowp + c4);
                    v.x = (c4 + 0 < kvq) ? v.x * inv : 0.f;
                    v.y = (c4 + 1 < kvq) ? v.y * inv : 0.f;
                    v.z = (c4 + 2 < kvq) ? v.z * inv : 0.f;
                    v.w = (c4 + 3 < kvq) ? v.w * inv : 0.f;
                }
                *(float4*)(rowp + c4) = v;
            }
        }
    }

    // out_seq epilogue from fragments: x + O/rowsum
    {
        float inv0 = 1.0f / rsums[m_base + qrow];
        float inv1 = 1.0f / rsums[m_base + qrow + 8];
        #pragma unroll
        for (int nt = 0; nt < 4; nt++) {
            int dv = n_base + nt * 8 + 2 * qcol;
            size_t off0 = (((size_t)(b_ << 10 | qg0)) << 10) + (h << 6) + dv;
            size_t off1 = (((size_t)(b_ << 10 | qg1)) << 10) + (h << 6) + dv;
            float2 x0 = *(const float2*)(x + off0);
            float2 x1 = *(const float2*)(x + off1);
            float2 o0, o1;
            o0.x = x0.x + acc_o[nt][0] * inv0;
            o0.y = x0.y + acc_o[nt][1] * inv0;
            o1.x = x1.x + acc_o[nt][2] * inv1;
            o1.y = x1.y + acc_o[nt][3] * inv1;
            *(float2*)(out_seq + off0) = o0;
            *(float2*)(out_seq + off1) = o1;
        }
    }
}

// ---------------------------------------------------------------------------
extern "C" void kernel_launch(void* const* d_in, const int* in_sizes, int n_in,
                              void* d_out, int out_size) {
    (void)in_sizes; (void)n_in; (void)out_size;
    const float* x     = (const float*)d_in[0];
    const int*   kvlen = (const int*)d_in[3];
    const float* gamma = (const float*)d_in[4];
    const float* beta  = (const float*)d_in[5];
    const float* Wq = (const float*)d_in[6];
    const float* bq = (const float*)d_in[7];
    const float* Wk = (const float*)d_in[8];
    const float* bk = (const float*)d_in[9];
    const float* Wv = (const float*)d_in[10];
    const float* bv = (const float*)d_in[11];

    float* out_seq  = (float*)d_out;
    float* out_attn = out_seq + (size_t)NB * NS * ND;

    ln_kernel<<<NM, 256>>>(x, gamma, beta);

    cudaFuncSetAttribute(qkv_gemm,
                         cudaFuncAttributeMaxDynamicSharedMemorySize, QKV_SMEM);
    qkv_gemm<<<dim3(8, 32, 3), 256, QKV_SMEM>>>(Wq, bq, Wk, bk, Wv, bv);

    cudaFuncSetAttribute(attn_kernel,
                         cudaFuncAttributeMaxDynamicSharedMemorySize, ATTN_SMEM);
    attn_kernel<<<dim3(16, 64), 256, ATTN_SMEM>>>(x, kvlen, out_seq, out_attn);
}

// round 8
// speedup vs baseline: 1.6595x; 1.6595x over previous
#include <cuda_runtime.h>
#include <cuda_fp16.h>
#include <cstdint>

// Problem constants
#define NB 4
#define NS 1024
#define ND 1024
#define NH 16
#define DH 64
#define NM (NB * NS)   // 4096 rows

// Scratch (allocation-free rule: __device__ globals)
__device__ __half g_xn[NM * ND];       // layernormed x, fp16, [4096][1024]
__device__ __half g_wt[3 * ND * ND];   // W^T fp16, [z][n][k]
__device__ __half g_qh[NM * ND];       // [B*H][S][64], PRE-SCALED by 0.125
__device__ __half g_kh[NM * ND];
__device__ __half g_vh[NM * ND];

// ---------------------------------------------------------------------------
// helpers
// ---------------------------------------------------------------------------
__device__ __forceinline__ void mma_f16(float c[4],
                                        uint32_t a0, uint32_t a1, uint32_t a2, uint32_t a3,
                                        uint32_t b0, uint32_t b1) {
    asm volatile(
        "mma.sync.aligned.m16n8k16.row.col.f32.f16.f16.f32 "
        "{%0,%1,%2,%3},{%4,%5,%6,%7},{%8,%9},{%0,%1,%2,%3};\n"
        : "+f"(c[0]), "+f"(c[1]), "+f"(c[2]), "+f"(c[3])
        : "r"(a0), "r"(a1), "r"(a2), "r"(a3), "r"(b0), "r"(b1));
}

__device__ __forceinline__ void ldsm4(uint32_t& r0, uint32_t& r1, uint32_t& r2, uint32_t& r3,
                                      uint32_t addr) {
    asm volatile("ldmatrix.sync.aligned.m8n8.x4.shared.b16 {%0,%1,%2,%3}, [%4];"
                 : "=r"(r0), "=r"(r1), "=r"(r2), "=r"(r3) : "r"(addr));
}
__device__ __forceinline__ void ldsm2(uint32_t& r0, uint32_t& r1, uint32_t addr) {
    asm volatile("ldmatrix.sync.aligned.m8n8.x2.shared.b16 {%0,%1}, [%2];"
                 : "=r"(r0), "=r"(r1) : "r"(addr));
}
__device__ __forceinline__ uint32_t smem_u32(const void* p) {
    return (uint32_t)__cvta_generic_to_shared(p);
}

// ---------------------------------------------------------------------------
// Kernel 1: LayerNorm -> fp16. One block per row, 256 threads.
// ---------------------------------------------------------------------------
__global__ void __launch_bounds__(256)
ln_kernel(const float* __restrict__ x,
          const float* __restrict__ gamma,
          const float* __restrict__ beta) {
    int row = blockIdx.x;
    int tid = threadIdx.x;
    const float4* xr = reinterpret_cast<const float4*>(x + (size_t)row * ND);
    float4 v = xr[tid];

    float s1 = v.x + v.y + v.z + v.w;
    float s2 = v.x * v.x + v.y * v.y + v.z * v.z + v.w * v.w;

    __shared__ float red1[8];
    __shared__ float red2[8];
    #pragma unroll
    for (int o = 16; o; o >>= 1) {
        s1 += __shfl_xor_sync(0xffffffffu, s1, o);
        s2 += __shfl_xor_sync(0xffffffffu, s2, o);
    }
    if ((tid & 31) == 0) { red1[tid >> 5] = s1; red2[tid >> 5] = s2; }
    __syncthreads();
    if (tid == 0) {
        float t1 = 0.f, t2 = 0.f;
        #pragma unroll
        for (int i = 0; i < 8; i++) { t1 += red1[i]; t2 += red2[i]; }
        red1[0] = t1; red2[0] = t2;
    }
    __syncthreads();
    float mu = red1[0] * (1.0f / ND);
    float var = red2[0] * (1.0f / ND) - mu * mu;
    float rstd = rsqrtf(var + 1e-5f);

    const float4 g4 = reinterpret_cast<const float4*>(gamma)[tid];
    const float4 b4 = reinterpret_cast<const float4*>(beta)[tid];
    float o0 = (v.x - mu) * rstd * g4.x + b4.x;
    float o1 = (v.y - mu) * rstd * g4.y + b4.y;
    float o2 = (v.z - mu) * rstd * g4.z + b4.z;
    float o3 = (v.w - mu) * rstd * g4.w + b4.w;

    size_t off = (size_t)row * ND + tid * 4;
    *reinterpret_cast<__half2*>(g_xn + off)     = __floats2half2_rn(o0, o1);
    *reinterpret_cast<__half2*>(g_xn + off + 2) = __floats2half2_rn(o2, o3);
}

// ---------------------------------------------------------------------------
// Kernel 1b: W transpose -> fp16. Wt[n][k] = W[k][n].
// grid (32 k-tiles, 32 n-tiles, 3), block 256 (32x8).
// ---------------------------------------------------------------------------
__global__ void __launch_bounds__(256)
wt_kernel(const float* __restrict__ Wq, const float* __restrict__ Wk,
          const float* __restrict__ Wv) {
    __shared__ float t[32][33];
    int z = blockIdx.z;
    const float* W = (z == 0) ? Wq : (z == 1) ? Wk : Wv;
    __half* oh = g_wt + (size_t)z * ND * ND;

    int k0 = blockIdx.x << 5, n0 = blockIdx.y << 5;
    int tx = threadIdx.x & 31, ty = threadIdx.x >> 5;

    #pragma unroll
    for (int i = 0; i < 32; i += 8)
        t[ty + i][tx] = W[(size_t)(k0 + ty + i) * ND + n0 + tx];
    __syncthreads();
    #pragma unroll
    for (int i = 0; i < 32; i += 8) {
        int n = ty + i;
        oh[(size_t)(n0 + n) * ND + k0 + tx] = __float2half_rn(t[tx][n]);
    }
}

// ---------------------------------------------------------------------------
// Kernel 2: QKV projection GEMM, fp16 m16n8k16 tensor-core.
// C = xn @ W + b; 128x128 tile, BK=64, 256 threads (8 warps, 2x4 grid,
// 64x32 per warp). A/B fp16 in smem (pitch 72 halves), ldmatrix fragments.
// Output fp16 into [B*H][S][64]; q pre-scaled by 0.125.
// ---------------------------------------------------------------------------
#define PITCH 72

__global__ void __launch_bounds__(256)
qkv_gemm(const float* __restrict__ bq, const float* __restrict__ bk,
         const float* __restrict__ bv) {
    __shared__ __half As[128 * PITCH];
    __shared__ __half Bs[128 * PITCH];

    int z = blockIdx.z;
    const float* bias = (z == 0) ? bq : (z == 1) ? bk : bv;
    __half* outp      = (z == 0) ? g_qh : (z == 1) ? g_kh : g_vh;
    float osc = (z == 0) ? 0.125f : 1.0f;
    const __half* W = g_wt + (size_t)z * ND * ND;

    int tid  = threadIdx.x;
    int lane = tid & 31;
    int warp = tid >> 5;
    int m_base = (warp & 1) * 64;
    int n_base = (warp >> 1) * 32;
    int qrow = lane >> 2;
    int qcol = lane & 3;

    int m0 = blockIdx.y << 7;
    int n0 = blockIdx.x << 7;

    // ldmatrix lane address components
    int a_row = (lane & 7) + ((lane >> 3) & 1) * 8;
    int a_kof = ((lane >> 4) & 1) * 8;
    int b_row = lane & 7;
    int b_kof = ((lane >> 3) & 1) * 8;

    uint32_t As_u = smem_u32(As);
    uint32_t Bs_u = smem_u32(Bs);

    float acc[4][4][4];
    #pragma unroll
    for (int mt = 0; mt < 4; mt++)
        #pragma unroll
        for (int nt = 0; nt < 4; nt++)
            #pragma unroll
            for (int r = 0; r < 4; r++) acc[mt][nt][r] = 0.f;

    int r = tid >> 3, u = tid & 7;   // 32 rows x 8x16B per pass
    const __half* agp = g_xn + (size_t)(m0 + r) * ND + u * 8;
    const __half* bgp = W + (size_t)(n0 + r) * ND + u * 8;

    uint4 av[4], bv4[4];
    #pragma unroll
    for (int i = 0; i < 4; i++) av[i]  = *(const uint4*)(agp + (size_t)(32 * i) * ND);
    #pragma unroll
    for (int i = 0; i < 4; i++) bv4[i] = *(const uint4*)(bgp + (size_t)(32 * i) * ND);

    for (int it = 0; it < 16; it++) {
        __syncthreads();
        #pragma unroll
        for (int i = 0; i < 4; i++)
            *(uint4*)&As[(r + 32 * i) * PITCH + u * 8] = av[i];
        #pragma unroll
        for (int i = 0; i < 4; i++)
            *(uint4*)&Bs[(r + 32 * i) * PITCH + u * 8] = bv4[i];
        __syncthreads();

        if (it + 1 < 16) {
            int kof = (it + 1) * 64;
            #pragma unroll
            for (int i = 0; i < 4; i++) av[i]  = *(const uint4*)(agp + (size_t)(32 * i) * ND + kof);
            #pragma unroll
            for (int i = 0; i < 4; i++) bv4[i] = *(const uint4*)(bgp + (size_t)(32 * i) * ND + kof);
        }

        #pragma unroll
        for (int ks = 0; ks < 4; ks++) {
            uint32_t af[4][4];
            #pragma unroll
            for (int mt = 0; mt < 4; mt++)
                ldsm4(af[mt][0], af[mt][1], af[mt][2], af[mt][3],
                      As_u + (uint32_t)(((m_base + mt * 16 + a_row) * PITCH + ks * 16 + a_kof) << 1));
            uint32_t bf[4][2];
            #pragma unroll
            for (int nt = 0; nt < 4; nt++)
                ldsm2(bf[nt][0], bf[nt][1],
                      Bs_u + (uint32_t)(((n_base + nt * 8 + b_row) * PITCH + ks * 16 + b_kof) << 1));
            #pragma unroll
            for (int mt = 0; mt < 4; mt++)
                #pragma unroll
                for (int nt = 0; nt < 4; nt++)
                    mma_f16(acc[mt][nt],
                            af[mt][0], af[mt][1], af[mt][2], af[mt][3],
                            bf[nt][0], bf[nt][1]);
        }
    }

    // epilogue: c0,c1 = (qrow, 2qcol..+1), c2,c3 = (qrow+8, ...)
    #pragma unroll
    for (int mt = 0; mt < 4; mt++) {
        #pragma unroll
        for (int nt = 0; nt < 4; nt++) {
            int col = n0 + n_base + nt * 8 + 2 * qcol;
            int h = col >> 6, d = col & 63;
            float bx = bias[col], by = bias[col + 1];
            #pragma unroll
            for (int half_ = 0; half_ < 2; half_++) {
                int row = m0 + m_base + mt * 16 + qrow + half_ * 8;
                int b_ = row >> 10, s = row & 1023;
                __half2 hv = __floats2half2_rn((acc[mt][nt][half_ * 2 + 0] + bx) * osc,
                                               (acc[mt][nt][half_ * 2 + 1] + by) * osc);
                *(__half2*)(outp + (size_t)(((b_ * NH + h) << 10) + s) * DH + d) = hv;
            }
        }
    }
}

// ---------------------------------------------------------------------------
// Kernel 3: attention, fp16 m16n8k16. grid (16 q-tiles, 64 bh), 256 threads.
// Warp w: rows [(w>>1)*16,+16) x cols [(w&1)*32,+32).
// Q prescaled by 0.125 -> exp(acc) directly. K natural layout is the B
// operand for S; V transposed to [dv][j] at load for PV.
// ---------------------------------------------------------------------------
__global__ void __launch_bounds__(256)
attn_kernel(const float* __restrict__ x,
            const int* __restrict__ kvlen,
            float* __restrict__ out_seq,
            float* __restrict__ out_attn) {
    __shared__ __half Qs[64 * PITCH];
    __shared__ __half Ks[64 * PITCH];
    __shared__ __half Vs[64 * PITCH];   // [dv][j]
    __shared__ __half Ps[64 * PITCH];
    __shared__ float rsums[64];

    int tid  = threadIdx.x;
    int lane = tid & 31;
    int warp = tid >> 5;
    int m_base = (warp >> 1) << 4;
    int n_base = (warp & 1) << 5;
    int qrow = lane >> 2;
    int qcol = lane & 3;

    int a_row = (lane & 7) + ((lane >> 3) & 1) * 8;
    int a_kof = ((lane >> 4) & 1) * 8;
    int b_row = lane & 7;
    int b_kof = ((lane >> 3) & 1) * 8;

    uint32_t Qs_u = smem_u32(Qs);
    uint32_t Ks_u = smem_u32(Ks);
    uint32_t Vs_u = smem_u32(Vs);
    uint32_t Ps_u = smem_u32(Ps);

    int bh = blockIdx.y;
    int b_ = bh >> 4, h = bh & 15;
    int q0 = blockIdx.x << 6;
    int kv = kvlen[b_];

    // load Q tile (fp16, already scaled)
    #pragma unroll
    for (int i = 0; i < 2; i++) {
        int idx = tid + 256 * i;
        int r = idx >> 3, u = idx & 7;
        *(uint4*)&Qs[r * PITCH + u * 8] =
            *(const uint4*)(g_qh + (size_t)(bh * NS + q0 + r) * DH + u * 8);
    }
    if (tid < 64) rsums[tid] = 0.f;

    float acc_o[4][4];
    #pragma unroll
    for (int nt = 0; nt < 4; nt++)
        #pragma unroll
        for (int r = 0; r < 4; r++) acc_o[nt][r] = 0.f;

    int qg0 = q0 + m_base + qrow;
    int qg1 = qg0 + 8;

    int jend = min(q0 + 64, kv);

    for (int j0 = 0; j0 < jend; j0 += 64) {
        __syncthreads();   // protect Ps/Ks/Vs reuse

        // K chunk (direct copy)
        #pragma unroll
        for (int i = 0; i < 2; i++) {
            int idx = tid + 256 * i;
            int r = idx >> 3, u = idx & 7;
            *(uint4*)&Ks[r * PITCH + u * 8] =
                *(const uint4*)(g_kh + (size_t)(bh * NS + j0 + r) * DH + u * 8);
        }
        // V chunk transposed: Vs[dv][j]
        {
            int jp = tid >> 3, dg = tid & 7;
            const __half* vb0 = g_vh + (size_t)(bh * NS + j0 + 2 * jp) * DH + dg * 8;
            uint4 va = *(const uint4*)vb0;
            uint4 vb = *(const uint4*)(vb0 + DH);
            const uint32_t* pa = (const uint32_t*)&va;
            const uint32_t* pb = (const uint32_t*)&vb;
            #pragma unroll
            for (int i = 0; i < 4; i++) {
                uint32_t lo = __byte_perm(pa[i], pb[i], 0x5410);
                uint32_t hi = __byte_perm(pa[i], pb[i], 0x7632);
                int dv = dg * 8 + 2 * i;
                *(uint32_t*)&Vs[dv * PITCH + 2 * jp]       = lo;
                *(uint32_t*)&Vs[(dv + 1) * PITCH + 2 * jp] = hi;
            }
        }
        __syncthreads();

        // S = Q K^T (warp: m16 x n32)
        float acc_s[4][4];
        #pragma unroll
        for (int nt = 0; nt < 4; nt++)
            #pragma unroll
            for (int r = 0; r < 4; r++) acc_s[nt][r] = 0.f;

        #pragma unroll
        for (int ks = 0; ks < 4; ks++) {
            uint32_t a0, a1, a2, a3;
            ldsm4(a0, a1, a2, a3,
                  Qs_u + (uint32_t)(((m_base + a_row) * PITCH + ks * 16 + a_kof) << 1));
            #pragma unroll
            for (int nt = 0; nt < 4; nt++) {
                uint32_t b0, b1;
                ldsm2(b0, b1,
                      Ks_u + (uint32_t)(((n_base + nt * 8 + b_row) * PITCH + ks * 16 + b_kof) << 1));
                mma_f16(acc_s[nt], a0, a1, a2, a3, b0, b1);
            }
        }

        // mask + exp -> Ps (fp16)
        #pragma unroll
        for (int nt = 0; nt < 4; nt++) {
            int kl = n_base + nt * 8 + 2 * qcol;
            int kg = j0 + kl;
            float e0 = (kg     <= qg0 && kg     < kv) ? __expf(acc_s[nt][0]) : 0.f;
            float e1 = (kg + 1 <= qg0 && kg + 1 < kv) ? __expf(acc_s[nt][1]) : 0.f;
            float e2 = (kg     <= qg1 && kg     < kv) ? __expf(acc_s[nt][2]) : 0.f;
            float e3 = (kg + 1 <= qg1 && kg + 1 < kv) ? __expf(acc_s[nt][3]) : 0.f;
            *(__half2*)&Ps[(m_base + qrow) * PITCH + kl]     = __floats2half2_rn(e0, e1);
            *(__half2*)&Ps[(m_base + qrow + 8) * PITCH + kl] = __floats2half2_rn(e2, e3);
        }
        __syncthreads();

        // rowsum + unnormalized global write (from fp16 Ps)
        {
            int row = tid >> 2, part = tid & 3;
            const __half2* hp = (const __half2*)&Ps[row * PITCH + part * 16];
            float2 f[8];
            #pragma unroll
            for (int i = 0; i < 8; i++) f[i] = __half22float2(hp[i]);
            float s = 0.f;
            #pragma unroll
            for (int i = 0; i < 8; i++) s += f[i].x + f[i].y;
            s += __shfl_xor_sync(0xffffffffu, s, 1);
            s += __shfl_xor_sync(0xffffffffu, s, 2);
            if (part == 0) rsums[row] += s;
            float* gp = out_attn + (((size_t)(bh << 10 | (q0 + row))) << 10) + j0 + part * 16;
            #pragma unroll
            for (int i = 0; i < 4; i++) {
                float4 w;
                w.x = f[2 * i].x; w.y = f[2 * i].y;
                w.z = f[2 * i + 1].x; w.w = f[2 * i + 1].y;
                *(float4*)(gp + 4 * i) = w;
            }
        }

        // O += P @ V
        #pragma unroll
        for (int ks = 0; ks < 4; ks++) {
            uint32_t a0, a1, a2, a3;
            ldsm4(a0, a1, a2, a3,
                  Ps_u + (uint32_t)(((m_base + a_row) * PITCH + ks * 16 + a_kof) << 1));
            #pragma unroll
            for (int nt = 0; nt < 4; nt++) {
                uint32_t b0, b1;
                ldsm2(b0, b1,
                      Vs_u + (uint32_t)(((n_base + nt * 8 + b_row) * PITCH + ks * 16 + b_kof) << 1));
                mma_f16(acc_o[nt], a0, a1, a2, a3, b0, b1);
            }
        }
    }
    __syncthreads();

    // normalize attn rows + zero-fill masked region
    {
        int ty = tid >> 4, tx = tid & 15;
        #pragma unroll
        for (int i = 0; i < 4; i++) {
            int rloc = ty * 4 + i;
            int q = q0 + rloc;
            float inv = 1.0f / rsums[rloc];
            float* rowp = out_attn + (((size_t)(bh << 10 | q)) << 10);
            int kvq = min(q + 1, kv);
            for (int c4 = tx * 4; c4 < 1024; c4 += 64) {
                float4 v;
                if (c4 + 4 <= kvq) {
                    v = *(float4*)(rowp + c4);
                    v.x *= inv; v.y *= inv; v.z *= inv; v.w *= inv;
                } else if (c4 >= kvq) {
                    v = make_float4(0.f, 0.f, 0.f, 0.f);
                } else {
                    v = *(float4*)(rowp + c4);
                    v.x = (c4 + 0 < kvq) ? v.x * inv : 0.f;
                    v.y = (c4 + 1 < kvq) ? v.y * inv : 0.f;
                    v.z = (c4 + 2 < kvq) ? v.z * inv : 0.f;
                    v.w = (c4 + 3 < kvq) ? v.w * inv : 0.f;
                }
                *(float4*)(rowp + c4) = v;
            }
        }
    }

    // out_seq epilogue: x + O/rowsum
    {
        float inv0 = 1.0f / rsums[m_base + qrow];
        float inv1 = 1.0f / rsums[m_base + qrow + 8];
        #pragma unroll
        for (int nt = 0; nt < 4; nt++) {
            int dv = n_base + nt * 8 + 2 * qcol;
            size_t off0 = (((size_t)(b_ << 10 | qg0)) << 10) + (h << 6) + dv;
            size_t off1 = (((size_t)(b_ << 10 | qg1)) << 10) + (h << 6) + dv;
            float2 x0 = *(const float2*)(x + off0);
            float2 x1 = *(const float2*)(x + off1);
            float2 o0, o1;
            o0.x = x0.x + acc_o[nt][0] * inv0;
            o0.y = x0.y + acc_o[nt][1] * inv0;
            o1.x = x1.x + acc_o[nt][2] * inv1;
            o1.y = x1.y + acc_o[nt][3] * inv1;
            *(float2*)(out_seq + off0) = o0;
            *(float2*)(out_seq + off1) = o1;
        }
    }
}

// ---------------------------------------------------------------------------
extern "C" void kernel_launch(void* const* d_in, const int* in_sizes, int n_in,
                              void* d_out, int out_size) {
    (void)in_sizes; (void)n_in; (void)out_size;
    const float* x     = (const float*)d_in[0];
    const int*   kvlen = (const int*)d_in[3];
    const float* gamma = (const float*)d_in[4];
    const float* beta  = (const float*)d_in[5];
    const float* Wq = (const float*)d_in[6];
    const float* bq = (const float*)d_in[7];
    const float* Wk = (const float*)d_in[8];
    const float* bk = (const float*)d_in[9];
    const float* Wv = (const float*)d_in[10];
    const float* bv = (const float*)d_in[11];

    float* out_seq  = (float*)d_out;
    float* out_attn = out_seq + (size_t)NB * NS * ND;

    ln_kernel<<<NM, 256>>>(x, gamma, beta);
    wt_kernel<<<dim3(32, 32, 3), 256>>>(Wq, Wk, Wv);
    qkv_gemm<<<dim3(8, 32, 3), 256>>>(bq, bk, bv);
    attn_kernel<<<dim3(16, 64), 256>>>(x, kvlen, out_seq, out_attn);
}

// round 9
// speedup vs baseline: 1.8265x; 1.1006x over previous
#include <cuda_runtime.h>
#include <cuda_fp16.h>
#include <cstdint>

// Problem constants
#define NB 4
#define NS 1024
#define ND 1024
#define NH 16
#define DH 64
#define NM (NB * NS)   // 4096 rows

// Scratch (allocation-free rule: __device__ globals)
__device__ __half g_xn[NM * ND];       // layernormed x, fp16, [4096][1024]
__device__ __half g_wt[3 * ND * ND];   // W^T fp16, [z][n][k]
__device__ __half g_qh[NM * ND];       // [B*H][S][64], PRE-SCALED by 0.125
__device__ __half g_kh[NM * ND];
__device__ __half g_vh[NM * ND];

// ---------------------------------------------------------------------------
// helpers
// ---------------------------------------------------------------------------
__device__ __forceinline__ void mma_f16(float c[4],
                                        uint32_t a0, uint32_t a1, uint32_t a2, uint32_t a3,
                                        uint32_t b0, uint32_t b1) {
    asm volatile(
        "mma.sync.aligned.m16n8k16.row.col.f32.f16.f16.f32 "
        "{%0,%1,%2,%3},{%4,%5,%6,%7},{%8,%9},{%0,%1,%2,%3};\n"
        : "+f"(c[0]), "+f"(c[1]), "+f"(c[2]), "+f"(c[3])
        : "r"(a0), "r"(a1), "r"(a2), "r"(a3), "r"(b0), "r"(b1));
}

__device__ __forceinline__ void ldsm4(uint32_t& r0, uint32_t& r1, uint32_t& r2, uint32_t& r3,
                                      uint32_t addr) {
    asm volatile("ldmatrix.sync.aligned.m8n8.x4.shared.b16 {%0,%1,%2,%3}, [%4];"
                 : "=r"(r0), "=r"(r1), "=r"(r2), "=r"(r3) : "r"(addr));
}
__device__ __forceinline__ void ldsm2(uint32_t& r0, uint32_t& r1, uint32_t addr) {
    asm volatile("ldmatrix.sync.aligned.m8n8.x2.shared.b16 {%0,%1}, [%2];"
                 : "=r"(r0), "=r"(r1) : "r"(addr));
}
__device__ __forceinline__ uint32_t smem_u32(const void* p) {
    return (uint32_t)__cvta_generic_to_shared(p);
}

// ---------------------------------------------------------------------------
// Kernel 1: LayerNorm -> fp16. One block per row, 256 threads.
// ---------------------------------------------------------------------------
__global__ void __launch_bounds__(256)
ln_kernel(const float* __restrict__ x,
          const float* __restrict__ gamma,
          const float* __restrict__ beta) {
    int row = blockIdx.x;
    int tid = threadIdx.x;
    const float4* xr = reinterpret_cast<const float4*>(x + (size_t)row * ND);
    float4 v = xr[tid];

    float s1 = v.x + v.y + v.z + v.w;
    float s2 = v.x * v.x + v.y * v.y + v.z * v.z + v.w * v.w;

    __shared__ float red1[8];
    __shared__ float red2[8];
    #pragma unroll
    for (int o = 16; o; o >>= 1) {
        s1 += __shfl_xor_sync(0xffffffffu, s1, o);
        s2 += __shfl_xor_sync(0xffffffffu, s2, o);
    }
    if ((tid & 31) == 0) { red1[tid >> 5] = s1; red2[tid >> 5] = s2; }
    __syncthreads();
    if (tid == 0) {
        float t1 = 0.f, t2 = 0.f;
        #pragma unroll
        for (int i = 0; i < 8; i++) { t1 += red1[i]; t2 += red2[i]; }
        red1[0] = t1; red2[0] = t2;
    }
    __syncthreads();
    float mu = red1[0] * (1.0f / ND);
    float var = red2[0] * (1.0f / ND) - mu * mu;
    float rstd = rsqrtf(var + 1e-5f);

    const float4 g4 = reinterpret_cast<const float4*>(gamma)[tid];
    const float4 b4 = reinterpret_cast<const float4*>(beta)[tid];
    float o0 = (v.x - mu) * rstd * g4.x + b4.x;
    float o1 = (v.y - mu) * rstd * g4.y + b4.y;
    float o2 = (v.z - mu) * rstd * g4.z + b4.z;
    float o3 = (v.w - mu) * rstd * g4.w + b4.w;

    size_t off = (size_t)row * ND + tid * 4;
    *reinterpret_cast<__half2*>(g_xn + off)     = __floats2half2_rn(o0, o1);
    *reinterpret_cast<__half2*>(g_xn + off + 2) = __floats2half2_rn(o2, o3);
}

// ---------------------------------------------------------------------------
// Kernel 1b: W transpose -> fp16. Wt[n][k] = W[k][n].
// ---------------------------------------------------------------------------
__global__ void __launch_bounds__(256)
wt_kernel(const float* __restrict__ Wq, const float* __restrict__ Wk,
          const float* __restrict__ Wv) {
    __shared__ float t[32][33];
    int z = blockIdx.z;
    const float* W = (z == 0) ? Wq : (z == 1) ? Wk : Wv;
    __half* oh = g_wt + (size_t)z * ND * ND;

    int k0 = blockIdx.x << 5, n0 = blockIdx.y << 5;
    int tx = threadIdx.x & 31, ty = threadIdx.x >> 5;

    #pragma unroll
    for (int i = 0; i < 32; i += 8)
        t[ty + i][tx] = W[(size_t)(k0 + ty + i) * ND + n0 + tx];
    __syncthreads();
    #pragma unroll
    for (int i = 0; i < 32; i += 8) {
        int n = ty + i;
        oh[(size_t)(n0 + n) * ND + k0 + tx] = __float2half_rn(t[tx][n]);
    }
}

// ---------------------------------------------------------------------------
// Kernel 2: QKV projection GEMM, fp16 m16n8k16 (unchanged from R8).
// ---------------------------------------------------------------------------
#define PITCH 72

__global__ void __launch_bounds__(256)
qkv_gemm(const float* __restrict__ bq, const float* __restrict__ bk,
         const float* __restrict__ bv) {
    __shared__ __half As[128 * PITCH];
    __shared__ __half Bs[128 * PITCH];

    int z = blockIdx.z;
    const float* bias = (z == 0) ? bq : (z == 1) ? bk : bv;
    __half* outp      = (z == 0) ? g_qh : (z == 1) ? g_kh : g_vh;
    float osc = (z == 0) ? 0.125f : 1.0f;
    const __half* W = g_wt + (size_t)z * ND * ND;

    int tid  = threadIdx.x;
    int lane = tid & 31;
    int warp = tid >> 5;
    int m_base = (warp & 1) * 64;
    int n_base = (warp >> 1) * 32;
    int qrow = lane >> 2;
    int qcol = lane & 3;

    int m0 = blockIdx.y << 7;
    int n0 = blockIdx.x << 7;

    int a_row = (lane & 7) + ((lane >> 3) & 1) * 8;
    int a_kof = ((lane >> 4) & 1) * 8;
    int b_row = lane & 7;
    int b_kof = ((lane >> 3) & 1) * 8;

    uint32_t As_u = smem_u32(As);
    uint32_t Bs_u = smem_u32(Bs);

    float acc[4][4][4];
    #pragma unroll
    for (int mt = 0; mt < 4; mt++)
        #pragma unroll
        for (int nt = 0; nt < 4; nt++)
            #pragma unroll
            for (int r = 0; r < 4; r++) acc[mt][nt][r] = 0.f;

    int r = tid >> 3, u = tid & 7;
    const __half* agp = g_xn + (size_t)(m0 + r) * ND + u * 8;
    const __half* bgp = W + (size_t)(n0 + r) * ND + u * 8;

    uint4 av[4], bv4[4];
    #pragma unroll
    for (int i = 0; i < 4; i++) av[i]  = *(const uint4*)(agp + (size_t)(32 * i) * ND);
    #pragma unroll
    for (int i = 0; i < 4; i++) bv4[i] = *(const uint4*)(bgp + (size_t)(32 * i) * ND);

    for (int it = 0; it < 16; it++) {
        __syncthreads();
        #pragma unroll
        for (int i = 0; i < 4; i++)
            *(uint4*)&As[(r + 32 * i) * PITCH + u * 8] = av[i];
        #pragma unroll
        for (int i = 0; i < 4; i++)
            *(uint4*)&Bs[(r + 32 * i) * PITCH + u * 8] = bv4[i];
        __syncthreads();

        if (it + 1 < 16) {
            int kof = (it + 1) * 64;
            #pragma unroll
            for (int i = 0; i < 4; i++) av[i]  = *(const uint4*)(agp + (size_t)(32 * i) * ND + kof);
            #pragma unroll
            for (int i = 0; i < 4; i++) bv4[i] = *(const uint4*)(bgp + (size_t)(32 * i) * ND + kof);
        }

        #pragma unroll
        for (int ks = 0; ks < 4; ks++) {
            uint32_t af[4][4];
            #pragma unroll
            for (int mt = 0; mt < 4; mt++)
                ldsm4(af[mt][0], af[mt][1], af[mt][2], af[mt][3],
                      As_u + (uint32_t)(((m_base + mt * 16 + a_row) * PITCH + ks * 16 + a_kof) << 1));
            uint32_t bf[4][2];
            #pragma unroll
            for (int nt = 0; nt < 4; nt++)
                ldsm2(bf[nt][0], bf[nt][1],
                      Bs_u + (uint32_t)(((n_base + nt * 8 + b_row) * PITCH + ks * 16 + b_kof) << 1));
            #pragma unroll
            for (int mt = 0; mt < 4; mt++)
                #pragma unroll
                for (int nt = 0; nt < 4; nt++)
                    mma_f16(acc[mt][nt],
                            af[mt][0], af[mt][1], af[mt][2], af[mt][3],
                            bf[nt][0], bf[nt][1]);
        }
    }

    #pragma unroll
    for (int mt = 0; mt < 4; mt++) {
        #pragma unroll
        for (int nt = 0; nt < 4; nt++) {
            int col = n0 + n_base + nt * 8 + 2 * qcol;
            int h = col >> 6, d = col & 63;
            float bx = bias[col], by = bias[col + 1];
            #pragma unroll
            for (int half_ = 0; half_ < 2; half_++) {
                int row = m0 + m_base + mt * 16 + qrow + half_ * 8;
                int b_ = row >> 10, s = row & 1023;
                __half2 hv = __floats2half2_rn((acc[mt][nt][half_ * 2 + 0] + bx) * osc,
                                               (acc[mt][nt][half_ * 2 + 1] + by) * osc);
                *(__half2*)(outp + (size_t)(((b_ * NH + h) << 10) + s) * DH + d) = hv;
            }
        }
    }
}

// ---------------------------------------------------------------------------
// Kernel 3: attention, fp16 mma, SINGLE-PASS attn output.
// grid (16 q-tiles heavy-first, 64 bh), 256 threads.
// Full P row-block (64 x 1024 fp16) kept in smem; rowsums from fragments;
// normalized attn written once at the end (zero-fill for uncomputed cols).
// ---------------------------------------------------------------------------
#define PPITCH 1048
#define ATTN_SMEM_B (9216 * 3 + 512 + 64 * PPITCH * 2)   // 162304

__global__ void __launch_bounds__(256)
attn_kernel(const float* __restrict__ x,
            const int* __restrict__ kvlen,
            float* __restrict__ out_seq,
            float* __restrict__ out_attn) {
    extern __shared__ char smc[];
    __half* Qs  = (__half*)smc;                 // [64][72]
    __half* Ks  = (__half*)(smc + 9216);        // [64][72]
    __half* Vs  = (__half*)(smc + 18432);       // [dv 64][72]
    float*  rsA = (float*)(smc + 27648);        // [2][64]
    __half* Ps  = (__half*)(smc + 28160);       // [64][PPITCH]

    int tid  = threadIdx.x;
    int lane = tid & 31;
    int warp = tid >> 5;
    int m_base = (warp >> 1) << 4;
    int n_base = (warp & 1) << 5;
    int qrow = lane >> 2;
    int qcol = lane & 3;

    int a_row = (lane & 7) + ((lane >> 3) & 1) * 8;
    int a_kof = ((lane >> 4) & 1) * 8;
    int b_row = lane & 7;
    int b_kof = ((lane >> 3) & 1) * 8;

    uint32_t Qs_u = smem_u32(Qs);
    uint32_t Ks_u = smem_u32(Ks);
    uint32_t Vs_u = smem_u32(Vs);
    uint32_t Ps_u = smem_u32(Ps);

    int bh = blockIdx.y;
    int b_ = bh >> 4, h = bh & 15;
    int q0 = (15 - blockIdx.x) << 6;            // heavy blocks first
    int kv = kvlen[b_];

    // load Q tile (fp16, pre-scaled by 0.125)
    #pragma unroll
    for (int i = 0; i < 2; i++) {
        int idx = tid + 256 * i;
        int r = idx >> 3, u = idx & 7;
        *(uint4*)&Qs[r * PITCH + u * 8] =
            *(const uint4*)(g_qh + (size_t)(bh * NS + q0 + r) * DH + u * 8);
    }
    if (tid < 128) rsA[tid] = 0.f;

    float acc_o[4][4];
    #pragma unroll
    for (int nt = 0; nt < 4; nt++)
        #pragma unroll
        for (int r = 0; r < 4; r++) acc_o[nt][r] = 0.f;

    int qg0 = q0 + m_base + qrow;
    int qg1 = qg0 + 8;

    int jend = min(q0 + 64, kv);
    int nch = (jend + 63) >> 6;

    const __half* kb = g_kh + (size_t)(bh * NS) * DH;
    const __half* vb = g_vh + (size_t)(bh * NS) * DH;
    int kr = tid >> 3, ku = tid & 7;

    uint4 kreg0, kreg1, vreg0, vreg1;
    #define ATTN_PREFETCH(j0_)                                                  \
        do {                                                                    \
            kreg0 = *(const uint4*)(kb + (size_t)((j0_) + kr) * DH + ku * 8);   \
            kreg1 = *(const uint4*)(kb + (size_t)((j0_) + kr + 32) * DH + ku * 8);\
            vreg0 = *(const uint4*)(vb + (size_t)((j0_) + 2 * kr) * DH + ku * 8);\
            vreg1 = *(const uint4*)(vb + (size_t)((j0_) + 2 * kr + 1) * DH + ku * 8);\
        } while (0)

    ATTN_PREFETCH(0);

    for (int c = 0; c < nch; c++) {
        int j0 = c << 6;
        int cbase = j0;
        __syncthreads();   // Ks/Vs free from previous chunk's mma

        *(uint4*)&Ks[kr * PITCH + ku * 8]        = kreg0;
        *(uint4*)&Ks[(kr + 32) * PITCH + ku * 8] = kreg1;
        {
            const uint32_t* pa = (const uint32_t*)&vreg0;
            const uint32_t* pb = (const uint32_t*)&vreg1;
            #pragma unroll
            for (int i = 0; i < 4; i++) {
                uint32_t lo = __byte_perm(pa[i], pb[i], 0x5410);
                uint32_t hi = __byte_perm(pa[i], pb[i], 0x7632);
                int dv = ku * 8 + 2 * i;
                *(uint32_t*)&Vs[dv * PITCH + 2 * kr]       = lo;
                *(uint32_t*)&Vs[(dv + 1) * PITCH + 2 * kr] = hi;
            }
        }
        __syncthreads();

        if (c + 1 < nch) ATTN_PREFETCH((c + 1) << 6);

        // S = Q K^T (warp: m16 x n32)
        float acc_s[4][4];
        #pragma unroll
        for (int nt = 0; nt < 4; nt++)
            #pragma unroll
            for (int r = 0; r < 4; r++) acc_s[nt][r] = 0.f;

        #pragma unroll
        for (int ks = 0; ks < 4; ks++) {
            uint32_t a0, a1, a2, a3;
            ldsm4(a0, a1, a2, a3,
                  Qs_u + (uint32_t)(((m_base + a_row) * PITCH + ks * 16 + a_kof) << 1));
            #pragma unroll
            for (int nt = 0; nt < 4; nt++) {
                uint32_t b0, b1;
                ldsm2(b0, b1,
                      Ks_u + (uint32_t)(((n_base + nt * 8 + b_row) * PITCH + ks * 16 + b_kof) << 1));
                mma_f16(acc_s[nt], a0, a1, a2, a3, b0, b1);
            }
        }

        // mask + exp -> Ps (fp16) ; rowsum from fp32 fragments
        float s0 = 0.f, s1 = 0.f;
        #pragma unroll
        for (int nt = 0; nt < 4; nt++) {
            int kl = n_base + nt * 8 + 2 * qcol;
            int kg = j0 + kl;
            float e0 = (kg     <= qg0 && kg     < kv) ? __expf(acc_s[nt][0]) : 0.f;
            float e1 = (kg + 1 <= qg0 && kg + 1 < kv) ? __expf(acc_s[nt][1]) : 0.f;
            float e2 = (kg     <= qg1 && kg     < kv) ? __expf(acc_s[nt][2]) : 0.f;
            float e3 = (kg + 1 <= qg1 && kg + 1 < kv) ? __expf(acc_s[nt][3]) : 0.f;
            s0 += e0 + e1;
            s1 += e2 + e3;
            *(__half2*)&Ps[(m_base + qrow) * PPITCH + cbase + kl]     = __floats2half2_rn(e0, e1);
            *(__half2*)&Ps[(m_base + qrow + 8) * PPITCH + cbase + kl] = __floats2half2_rn(e2, e3);
        }
        s0 += __shfl_xor_sync(0xffffffffu, s0, 1);
        s0 += __shfl_xor_sync(0xffffffffu, s0, 2);
        s1 += __shfl_xor_sync(0xffffffffu, s1, 1);
        s1 += __shfl_xor_sync(0xffffffffu, s1, 2);
        if (qcol == 0) {
            int nh = (warp & 1) * 64;
            rsA[nh + m_base + qrow]     += s0;
            rsA[nh + m_base + qrow + 8] += s1;
        }
        __syncthreads();   // pair-warp's P columns visible for PV

        // O += P @ V
        #pragma unroll
        for (int ks = 0; ks < 4; ks++) {
            uint32_t a0, a1, a2, a3;
            ldsm4(a0, a1, a2, a3,
                  Ps_u + (uint32_t)(((m_base + a_row) * PPITCH + cbase + ks * 16 + a_kof) << 1));
            #pragma unroll
            for (int nt = 0; nt < 4; nt++) {
                uint32_t b0, b1;
                ldsm2(b0, b1,
                      Vs_u + (uint32_t)(((n_base + nt * 8 + b_row) * PITCH + ks * 16 + b_kof) << 1));
                mma_f16(acc_o[nt], a0, a1, a2, a3, b0, b1);
            }
        }
    }
    #undef ATTN_PREFETCH
    __syncthreads();

    // single-pass normalized attn write (+ zero-fill beyond computed cols)
    {
        int cend = nch << 6;
        for (int rr = warp; rr < 64; rr += 8) {
            int q = q0 + rr;
            float inv = 1.0f / (rsA[rr] + rsA[64 + rr]);
            float* rowp = out_attn + (((size_t)(bh << 10 | q)) << 10);
            const __half* prow = Ps + rr * PPITCH;
            #pragma unroll
            for (int i = 0; i < 8; i++) {
                int col = i * 128 + lane * 4;
                float4 w4;
                if (col < cend) {
                    uint2 uu = *(const uint2*)(prow + col);
                    __half2 h0 = *(__half2*)&uu.x;
                    __half2 h1 = *(__half2*)&uu.y;
                    float2 f0 = __half22float2(h0);
                    float2 f1 = __half22float2(h1);
                    w4.x = f0.x * inv; w4.y = f0.y * inv;
                    w4.z = f1.x * inv; w4.w = f1.y * inv;
                } else {
                    w4 = make_float4(0.f, 0.f, 0.f, 0.f);
                }
                *(float4*)(rowp + col) = w4;
            }
        }
    }

    // out_seq epilogue: x + O/rowsum
    {
        float inv0 = 1.0f / (rsA[m_base + qrow] + rsA[64 + m_base + qrow]);
        float inv1 = 1.0f / (rsA[m_base + qrow + 8] + rsA[64 + m_base + qrow + 8]);
        #pragma unroll
        for (int nt = 0; nt < 4; nt++) {
            int dv = n_base + nt * 8 + 2 * qcol;
            size_t off0 = (((size_t)(b_ << 10 | qg0)) << 10) + (h << 6) + dv;
            size_t off1 = (((size_t)(b_ << 10 | qg1)) << 10) + (h << 6) + dv;
            float2 x0 = *(const float2*)(x + off0);
            float2 x1 = *(const float2*)(x + off1);
            float2 o0, o1;
            o0.x = x0.x + acc_o[nt][0] * inv0;
            o0.y = x0.y + acc_o[nt][1] * inv0;
            o1.x = x1.x + acc_o[nt][2] * inv1;
            o1.y = x1.y + acc_o[nt][3] * inv1;
            *(float2*)(out_seq + off0) = o0;
            *(float2*)(out_seq + off1) = o1;
        }
    }
}

// ---------------------------------------------------------------------------
extern "C" void kernel_launch(void* const* d_in, const int* in_sizes, int n_in,
                              void* d_out, int out_size) {
    (void)in_sizes; (void)n_in; (void)out_size;
    const float* x     = (const float*)d_in[0];
    const int*   kvlen = (const int*)d_in[3];
    const float* gamma = (const float*)d_in[4];
    const float* beta  = (const float*)d_in[5];
    const float* Wq = (const float*)d_in[6];
    const float* bq = (const float*)d_in[7];
    const float* Wk = (const float*)d_in[8];
    const float* bk = (const float*)d_in[9];
    const float* Wv = (const float*)d_in[10];
    const float* bv = (const float*)d_in[11];

    float* out_seq  = (float*)d_out;
    float* out_attn = out_seq + (size_t)NB * NS * ND;

    ln_kernel<<<NM, 256>>>(x, gamma, beta);
    wt_kernel<<<dim3(32, 32, 3), 256>>>(Wq, Wk, Wv);
    qkv_gemm<<<dim3(8, 32, 3), 256>>>(bq, bk, bv);

    cudaFuncSetAttribute(attn_kernel,
                         cudaFuncAttributeMaxDynamicSharedMemorySize, ATTN_SMEM_B);
    attn_kernel<<<dim3(16, 64), 256, ATTN_SMEM_B>>>(x, kvlen, out_seq, out_attn);
}

// round 12
// speedup vs baseline: 1.8454x; 1.0104x over previous
#include <cuda_runtime.h>
#include <cuda_fp16.h>
#include <cstdint>

// Problem constants
#define NB 4
#define NS 1024
#define ND 1024
#define NH 16
#define DH 64
#define NM (NB * NS)   // 4096 rows

// Scratch (allocation-free rule: __device__ globals)
__device__ __half g_xn[NM * ND];       // layernormed x, fp16, [4096][1024]
__device__ __half g_wt[3 * ND * ND];   // W^T fp16, [z][n][k]
__device__ __half g_qh[NM * ND];       // [B*H][S][64], PRE-SCALED by 0.125
__device__ __half g_kh[NM * ND];
__device__ __half g_vh[NM * ND];

// ---------------------------------------------------------------------------
// helpers
// ---------------------------------------------------------------------------
__device__ __forceinline__ void mma_f16(float c[4],
                                        uint32_t a0, uint32_t a1, uint32_t a2, uint32_t a3,
                                        uint32_t b0, uint32_t b1) {
    asm volatile(
        "mma.sync.aligned.m16n8k16.row.col.f32.f16.f16.f32 "
        "{%0,%1,%2,%3},{%4,%5,%6,%7},{%8,%9},{%0,%1,%2,%3};\n"
        : "+f"(c[0]), "+f"(c[1]), "+f"(c[2]), "+f"(c[3])
        : "r"(a0), "r"(a1), "r"(a2), "r"(a3), "r"(b0), "r"(b1));
}

__device__ __forceinline__ void ldsm4(uint32_t& r0, uint32_t& r1, uint32_t& r2, uint32_t& r3,
                                      uint32_t addr) {
    asm volatile("ldmatrix.sync.aligned.m8n8.x4.shared.b16 {%0,%1,%2,%3}, [%4];"
                 : "=r"(r0), "=r"(r1), "=r"(r2), "=r"(r3) : "r"(addr));
}
__device__ __forceinline__ void ldsm2(uint32_t& r0, uint32_t& r1, uint32_t addr) {
    asm volatile("ldmatrix.sync.aligned.m8n8.x2.shared.b16 {%0,%1}, [%2];"
                 : "=r"(r0), "=r"(r1) : "r"(addr));
}
__device__ __forceinline__ uint32_t smem_u32(const void* p) {
    return (uint32_t)__cvta_generic_to_shared(p);
}

// ---------------------------------------------------------------------------
// Kernel 1: LayerNorm -> fp16. One block per row, 256 threads.
// ---------------------------------------------------------------------------
__global__ void __launch_bounds__(256)
ln_kernel(const float* __restrict__ x,
          const float* __restrict__ gamma,
          const float* __restrict__ beta) {
    int row = blockIdx.x;
    int tid = threadIdx.x;
    const float4* xr = reinterpret_cast<const float4*>(x + (size_t)row * ND);
    float4 v = xr[tid];

    float s1 = v.x + v.y + v.z + v.w;
    float s2 = v.x * v.x + v.y * v.y + v.z * v.z + v.w * v.w;

    __shared__ float red1[8];
    __shared__ float red2[8];
    #pragma unroll
    for (int o = 16; o; o >>= 1) {
        s1 += __shfl_xor_sync(0xffffffffu, s1, o);
        s2 += __shfl_xor_sync(0xffffffffu, s2, o);
    }
    if ((tid & 31) == 0) { red1[tid >> 5] = s1; red2[tid >> 5] = s2; }
    __syncthreads();
    if (tid == 0) {
        float t1 = 0.f, t2 = 0.f;
        #pragma unroll
        for (int i = 0; i < 8; i++) { t1 += red1[i]; t2 += red2[i]; }
        red1[0] = t1; red2[0] = t2;
    }
    __syncthreads();
    float mu = red1[0] * (1.0f / ND);
    float var = red2[0] * (1.0f / ND) - mu * mu;
    float rstd = rsqrtf(var + 1e-5f);

    const float4 g4 = reinterpret_cast<const float4*>(gamma)[tid];
    const float4 b4 = reinterpret_cast<const float4*>(beta)[tid];
    float o0 = (v.x - mu) * rstd * g4.x + b4.x;
    float o1 = (v.y - mu) * rstd * g4.y + b4.y;
    float o2 = (v.z - mu) * rstd * g4.z + b4.z;
    float o3 = (v.w - mu) * rstd * g4.w + b4.w;

    size_t off = (size_t)row * ND + tid * 4;
    *reinterpret_cast<__half2*>(g_xn + off)     = __floats2half2_rn(o0, o1);
    *reinterpret_cast<__half2*>(g_xn + off + 2) = __floats2half2_rn(o2, o3);
}

// ---------------------------------------------------------------------------
// Kernel 1b: W transpose -> fp16. Wt[n][k] = W[k][n].
// ---------------------------------------------------------------------------
__global__ void __launch_bounds__(256)
wt_kernel(const float* __restrict__ Wq, const float* __restrict__ Wk,
          const float* __restrict__ Wv) {
    __shared__ float t[32][33];
    int z = blockIdx.z;
    const float* W = (z == 0) ? Wq : (z == 1) ? Wk : Wv;
    __half* oh = g_wt + (size_t)z * ND * ND;

    int k0 = blockIdx.x << 5, n0 = blockIdx.y << 5;
    int tx = threadIdx.x & 31, ty = threadIdx.x >> 5;

    #pragma unroll
    for (int i = 0; i < 32; i += 8)
        t[ty + i][tx] = W[(size_t)(k0 + ty + i) * ND + n0 + tx];
    __syncthreads();
    #pragma unroll
    for (int i = 0; i < 32; i += 8) {
        int n = ty + i;
        oh[(size_t)(n0 + n) * ND + k0 + tx] = __float2half_rn(t[tx][n]);
    }
}

// ---------------------------------------------------------------------------
// Kernel 2: QKV projection GEMM, fp16 m16n8k16 (unchanged from R8).
// ---------------------------------------------------------------------------
#define PITCH 72

__global__ void __launch_bounds__(256)
qkv_gemm(const float* __restrict__ bq, const float* __restrict__ bk,
         const float* __restrict__ bv) {
    __shared__ __half As[128 * PITCH];
    __shared__ __half Bs[128 * PITCH];

    int z = blockIdx.z;
    const float* bias = (z == 0) ? bq : (z == 1) ? bk : bv;
    __half* outp      = (z == 0) ? g_qh : (z == 1) ? g_kh : g_vh;
    float osc = (z == 0) ? 0.125f : 1.0f;
    const __half* W = g_wt + (size_t)z * ND * ND;

    int tid  = threadIdx.x;
    int lane = tid & 31;
    int warp = tid >> 5;
    int m_base = (warp & 1) * 64;
    int n_base = (warp >> 1) * 32;
    int qrow = lane >> 2;
    int qcol = lane & 3;

    int m0 = blockIdx.y << 7;
    int n0 = blockIdx.x << 7;

    int a_row = (lane & 7) + ((lane >> 3) & 1) * 8;
    int a_kof = ((lane >> 4) & 1) * 8;
    int b_row = lane & 7;
    int b_kof = ((lane >> 3) & 1) * 8;

    uint32_t As_u = smem_u32(As);
    uint32_t Bs_u = smem_u32(Bs);

    float acc[4][4][4];
    #pragma unroll
    for (int mt = 0; mt < 4; mt++)
        #pragma unroll
        for (int nt = 0; nt < 4; nt++)
            #pragma unroll
            for (int r = 0; r < 4; r++) acc[mt][nt][r] = 0.f;

    int r = tid >> 3, u = tid & 7;
    const __half* agp = g_xn + (size_t)(m0 + r) * ND + u * 8;
    const __half* bgp = W + (size_t)(n0 + r) * ND + u * 8;

    uint4 av[4], bv4[4];
    #pragma unroll
    for (int i = 0; i < 4; i++) av[i]  = *(const uint4*)(agp + (size_t)(32 * i) * ND);
    #pragma unroll
    for (int i = 0; i < 4; i++) bv4[i] = *(const uint4*)(bgp + (size_t)(32 * i) * ND);

    for (int it = 0; it < 16; it++) {
        __syncthreads();
        #pragma unroll
        for (int i = 0; i < 4; i++)
            *(uint4*)&As[(r + 32 * i) * PITCH + u * 8] = av[i];
        #pragma unroll
        for (int i = 0; i < 4; i++)
            *(uint4*)&Bs[(r + 32 * i) * PITCH + u * 8] = bv4[i];
        __syncthreads();

        if (it + 1 < 16) {
            int kof = (it + 1) * 64;
            #pragma unroll
            for (int i = 0; i < 4; i++) av[i]  = *(const uint4*)(agp + (size_t)(32 * i) * ND + kof);
            #pragma unroll
            for (int i = 0; i < 4; i++) bv4[i] = *(const uint4*)(bgp + (size_t)(32 * i) * ND + kof);
        }

        #pragma unroll
        for (int ks = 0; ks < 4; ks++) {
            uint32_t af[4][4];
            #pragma unroll
            for (int mt = 0; mt < 4; mt++)
                ldsm4(af[mt][0], af[mt][1], af[mt][2], af[mt][3],
                      As_u + (uint32_t)(((m_base + mt * 16 + a_row) * PITCH + ks * 16 + a_kof) << 1));
            uint32_t bf[4][2];
            #pragma unroll
            for (int nt = 0; nt < 4; nt++)
                ldsm2(bf[nt][0], bf[nt][1],
                      Bs_u + (uint32_t)(((n_base + nt * 8 + b_row) * PITCH + ks * 16 + b_kof) << 1));
            #pragma unroll
            for (int mt = 0; mt < 4; mt++)
                #pragma unroll
                for (int nt = 0; nt < 4; nt++)
                    mma_f16(acc[mt][nt],
                            af[mt][0], af[mt][1], af[mt][2], af[mt][3],
                            bf[nt][0], bf[nt][1]);
        }
    }

    #pragma unroll
    for (int mt = 0; mt < 4; mt++) {
        #pragma unroll
        for (int nt = 0; nt < 4; nt++) {
            int col = n0 + n_base + nt * 8 + 2 * qcol;
            int h = col >> 6, d = col & 63;
            float bx = bias[col], by = bias[col + 1];
            #pragma unroll
            for (int half_ = 0; half_ < 2; half_++) {
                int row = m0 + m_base + mt * 16 + qrow + half_ * 8;
                int b_ = row >> 10, s = row & 1023;
                __half2 hv = __floats2half2_rn((acc[mt][nt][half_ * 2 + 0] + bx) * osc,
                                               (acc[mt][nt][half_ * 2 + 1] + by) * osc);
                *(__half2*)(outp + (size_t)(((b_ * NH + h) << 10) + s) * DH + d) = hv;
            }
        }
    }
}

// ---------------------------------------------------------------------------
// Kernel 3: attention, fp16 mma, single-pass output, 512 threads (16 warps).
// Warp grid 4x4 over the 64x64 tile: warp w owns rows [(w>>2)*16,+16) x
// cols [(w&3)*16,+16). Same smem as R9; occupancy 12.4% -> 25%.
// ---------------------------------------------------------------------------
#define PPITCH 1048
#define ATTN_SMEM_B (9216 * 3 + 1024 + 64 * PPITCH * 2)   // 162816

__global__ void __launch_bounds__(512)
attn_kernel(const float* __restrict__ x,
            const int* __restrict__ kvlen,
            float* __restrict__ out_seq,
            float* __restrict__ out_attn) {
    extern __shared__ char smc[];
    __half* Qs  = (__half*)smc;                 // [64][72]
    __half* Ks  = (__half*)(smc + 9216);        // [64][72]
    __half* Vs  = (__half*)(smc + 18432);       // [dv 64][72]
    float*  rsA = (float*)(smc + 27648);        // [4][64] column-quarter partials
    __half* Ps  = (__half*)(smc + 28672);       // [64][PPITCH]

    int tid  = threadIdx.x;
    int lane = tid & 31;
    int warp = tid >> 5;                        // 0..15
    int m_base = (warp >> 2) << 4;              // 0,16,32,48
    int n_base = (warp & 3) << 4;               // 0,16,32,48
    int qrow = lane >> 2;
    int qcol = lane & 3;

    int a_row = (lane & 7) + ((lane >> 3) & 1) * 8;
    int a_kof = ((lane >> 4) & 1) * 8;
    int b_row = lane & 7;
    int b_kof = ((lane >> 3) & 1) * 8;

    uint32_t Qs_u = smem_u32(Qs);
    uint32_t Ks_u = smem_u32(Ks);
    uint32_t Vs_u = smem_u32(Vs);
    uint32_t Ps_u = smem_u32(Ps);

    int bh = blockIdx.y;
    int b_ = bh >> 4, h = bh & 15;
    int q0 = (15 - blockIdx.x) << 6;            // heavy blocks first
    int kv = kvlen[b_];

    // load Q tile: one uint4 per thread (64 rows x 8 groups = 512)
    {
        int r = tid >> 3, u = tid & 7;
        *(uint4*)&Qs[r * PITCH + u * 8] =
            *(const uint4*)(g_qh + (size_t)(bh * NS + q0 + r) * DH + u * 8);
    }
    if (tid < 256) rsA[tid] = 0.f;

    float acc_o[2][4];
    #pragma unroll
    for (int nt = 0; nt < 2; nt++)
        #pragma unroll
        for (int r = 0; r < 4; r++) acc_o[nt][r] = 0.f;

    int qg0 = q0 + m_base + qrow;
    int qg1 = qg0 + 8;

    int jend = min(q0 + 64, kv);
    int nch = (jend + 63) >> 6;

    const __half* kb = g_kh + (size_t)(bh * NS) * DH;
    const __half* vb = g_vh + (size_t)(bh * NS) * DH;
    int kr = tid >> 3, ku = tid & 7;            // K: row 0..63, group 0..7
    int vp = (tid & 255) >> 3, vu = tid & 7;    // V (tid<256): pair 0..31

    uint4 kreg, vreg0, vreg1;
    #define ATTN_PREFETCH(j0_)                                                   \
        do {                                                                     \
            kreg = *(const uint4*)(kb + (size_t)((j0_) + kr) * DH + ku * 8);     \
            if (tid < 256) {                                                     \
                vreg0 = *(const uint4*)(vb + (size_t)((j0_) + 2 * vp) * DH + vu * 8);     \
                vreg1 = *(const uint4*)(vb + (size_t)((j0_) + 2 * vp + 1) * DH + vu * 8); \
            }                                                                    \
        } while (0)

    ATTN_PREFETCH(0);

    for (int c = 0; c < nch; c++) {
        int j0 = c << 6;
        __syncthreads();   // Ks/Vs free from previous chunk's mma

        *(uint4*)&Ks[kr * PITCH + ku * 8] = kreg;
        if (tid < 256) {
            const uint32_t* pa = (const uint32_t*)&vreg0;
            const uint32_t* pb = (const uint32_t*)&vreg1;
            #pragma unroll
            for (int i = 0; i < 4; i++) {
                uint32_t lo = __byte_perm(pa[i], pb[i], 0x5410);
                uint32_t hi = __byte_perm(pa[i], pb[i], 0x7632);
                int dv = vu * 8 + 2 * i;
                *(uint32_t*)&Vs[dv * PITCH + 2 * vp]       = lo;
                *(uint32_t*)&Vs[(dv + 1) * PITCH + 2 * vp] = hi;
            }
        }
        __syncthreads();

        if (c + 1 < nch) ATTN_PREFETCH((c + 1) << 6);

        // S = Q K^T (warp: m16 x n16)
        float acc_s[2][4];
        #pragma unroll
        for (int nt = 0; nt < 2; nt++)
            #pragma unroll
            for (int r = 0; r < 4; r++) acc_s[nt][r] = 0.f;

        #pragma unroll
        for (int ks = 0; ks < 4; ks++) {
            uint32_t a0, a1, a2, a3;
            ldsm4(a0, a1, a2, a3,
                  Qs_u + (uint32_t)(((m_base + a_row) * PITCH + ks * 16 + a_kof) << 1));
            #pragma unroll
            for (int nt = 0; nt < 2; nt++) {
                uint32_t b0, b1;
                ldsm2(b0, b1,
                      Ks_u + (uint32_t)(((n_base + nt * 8 + b_row) * PITCH + ks * 16 + b_kof) << 1));
                mma_f16(acc_s[nt], a0, a1, a2, a3, b0, b1);
            }
        }

        // mask + exp -> Ps (fp16) ; rowsum from fp32 fragments
        float s0 = 0.f, s1 = 0.f;
        #pragma unroll
        for (int nt = 0; nt < 2; nt++) {
            int kl = n_base + nt * 8 + 2 * qcol;
            int kg = j0 + kl;
            float e0 = (kg     <= qg0 && kg     < kv) ? __expf(acc_s[nt][0]) : 0.f;
            float e1 = (kg + 1 <= qg0 && kg + 1 < kv) ? __expf(acc_s[nt][1]) : 0.f;
            float e2 = (kg     <= qg1 && kg     < kv) ? __expf(acc_s[nt][2]) : 0.f;
            float e3 = (kg + 1 <= qg1 && kg + 1 < kv) ? __expf(acc_s[nt][3]) : 0.f;
            s0 += e0 + e1;
            s1 += e2 + e3;
            *(__half2*)&Ps[(m_base + qrow) * PPITCH + j0 + kl]     = __floats2half2_rn(e0, e1);
            *(__half2*)&Ps[(m_base + qrow + 8) * PPITCH + j0 + kl] = __floats2half2_rn(e2, e3);
        }
        s0 += __shfl_xor_sync(0xffffffffu, s0, 1);
        s0 += __shfl_xor_sync(0xffffffffu, s0, 2);
        s1 += __shfl_xor_sync(0xffffffffu, s1, 1);
        s1 += __shfl_xor_sync(0xffffffffu, s1, 2);
        if (qcol == 0) {
            int nh = (warp & 3) << 6;
            rsA[nh + m_base + qrow]     += s0;
            rsA[nh + m_base + qrow + 8] += s1;
        }
        __syncthreads();   // other warps' P columns visible for PV

        // O += P @ V   (A: Ps rows m_base..+16 over this chunk's 64 cols;
        //               B: Vs rows n_base..+16 = dv slice)
        #pragma unroll
        for (int ks = 0; ks < 4; ks++) {
            uint32_t a0, a1, a2, a3;
            ldsm4(a0, a1, a2, a3,
                  Ps_u + (uint32_t)(((m_base + a_row) * PPITCH + j0 + ks * 16 + a_kof) << 1));
            #pragma unroll
            for (int nt = 0; nt < 2; nt++) {
                uint32_t b0, b1;
                ldsm2(b0, b1,
                      Vs_u + (uint32_t)(((n_base + nt * 8 + b_row) * PITCH + ks * 16 + b_kof) << 1));
                mma_f16(acc_o[nt], a0, a1, a2, a3, b0, b1);
            }
        }
    }
    #undef ATTN_PREFETCH
    __syncthreads();

    // single-pass normalized attn write (+ zero-fill beyond computed cols)
    {
        int cend = nch << 6;
        for (int rr = warp; rr < 64; rr += 16) {
            int q = q0 + rr;
            float inv = 1.0f / (rsA[rr] + rsA[64 + rr] + rsA[128 + rr] + rsA[192 + rr]);
            float* rowp = out_attn + (((size_t)(bh << 10 | q)) << 10);
            const __half* prow = Ps + rr * PPITCH;
            #pragma unroll
            for (int i = 0; i < 8; i++) {
                int col = i * 128 + lane * 4;
                float4 w4;
                if (col < cend) {
                    uint2 uu = *(const uint2*)(prow + col);
                    __half2 h0 = *(__half2*)&uu.x;
                    __half2 h1 = *(__half2*)&uu.y;
                    float2 f0 = __half22float2(h0);
                    float2 f1 = __half22float2(h1);
                    w4.x = f0.x * inv; w4.y = f0.y * inv;
                    w4.z = f1.x * inv; w4.w = f1.y * inv;
                } else {
                    w4 = make_float4(0.f, 0.f, 0.f, 0.f);
                }
                *(float4*)(rowp + col) = w4;
            }
        }
    }

    // out_seq epilogue: x + O/rowsum
    {
        int r0i = m_base + qrow, r1i = r0i + 8;
        float inv0 = 1.0f / (rsA[r0i] + rsA[64 + r0i] + rsA[128 + r0i] + rsA[192 + r0i]);
        float inv1 = 1.0f / (rsA[r1i] + rsA[64 + r1i] + rsA[128 + r1i] + rsA[192 + r1i]);
        #pragma unroll
        for (int nt = 0; nt < 2; nt++) {
            int dv = n_base + nt * 8 + 2 * qcol;
            size_t off0 = (((size_t)(b_ << 10 | qg0)) << 10) + (h << 6) + dv;
            size_t off1 = (((size_t)(b_ << 10 | qg1)) << 10) + (h << 6) + dv;
            float2 x0 = *(const float2*)(x + off0);
            float2 x1 = *(const float2*)(x + off1);
            float2 o0, o1;
            o0.x = x0.x + acc_o[nt][0] * inv0;
            o0.y = x0.y + acc_o[nt][1] * inv0;
            o1.x = x1.x + acc_o[nt][2] * inv1;
            o1.y = x1.y + acc_o[nt][3] * inv1;
            *(float2*)(out_seq + off0) = o0;
            *(float2*)(out_seq + off1) = o1;
        }
    }
}

// ---------------------------------------------------------------------------
extern "C" void kernel_launch(void* const* d_in, const int* in_sizes, int n_in,
                              void* d_out, int out_size) {
    (void)in_sizes; (void)n_in; (void)out_size;
    const float* x     = (const float*)d_in[0];
    const int*   kvlen = (const int*)d_in[3];
    const float* gamma = (const float*)d_in[4];
    const float* beta  = (const float*)d_in[5];
    const float* Wq = (const float*)d_in[6];
    const float* bq = (const float*)d_in[7];
    const float* Wk = (const float*)d_in[8];
    const float* bk = (const float*)d_in[9];
    const float* Wv = (const float*)d_in[10];
    const float* bv = (const float*)d_in[11];

    float* out_seq  = (float*)d_out;
    float* out_attn = out_seq + (size_t)NB * NS * ND;

    ln_kernel<<<NM, 256>>>(x, gamma, beta);
    wt_kernel<<<dim3(32, 32, 3), 256>>>(Wq, Wk, Wv);
    qkv_gemm<<<dim3(8, 32, 3), 256>>>(bq, bk, bv);

    cudaFuncSetAttribute(attn_kernel,
                         cudaFuncAttributeMaxDynamicSharedMemorySize, ATTN_SMEM_B);
    attn_kernel<<<dim3(16, 64), 512, ATTN_SMEM_B>>>(x, kvlen, out_seq, out_attn);
}